// round 12
// baseline (speedup 1.0000x reference)
#include <cuda_runtime.h>
#include <cstdint>

// ActionSmoothingLoss: segmented log-softmax KL
// NVEC = (3,3,4,25,25,8), A = 68, W = 524288
// TMA bulk + mbarrier 3-stage ring; 2 CTAs/SM (104.4 KB smem each).

#define A_DIM        68
#define NSEG         6
#define BLOCK        128
#define RPS          128                       // rows per stage
#define STAGE_FLOATS (RPS * A_DIM)             // 8704
#define STAGE_BYTES  (STAGE_FLOATS * 4)        // 34816
#define NSTAGES      3
#define GRID_MAX     296                       // 2 blocks per SM

__device__ double g_part[GRID_MAX];
__device__ unsigned int g_count = 0;           // returns to 0 each call

#define SEG_OF(k) ((k) < 3 ? 0 : (k) < 6 ? 1 : (k) < 10 ? 2 : (k) < 35 ? 3 : (k) < 60 ? 4 : 5)

__device__ __forceinline__ uint32_t s2u(const void* p) {
    return (uint32_t)__cvta_generic_to_shared(p);
}
__device__ __forceinline__ void mbar_init(uint32_t a, uint32_t cnt) {
    asm volatile("mbarrier.init.shared.b64 [%0], %1;" :: "r"(a), "r"(cnt) : "memory");
}
__device__ __forceinline__ void mbar_expect_tx(uint32_t a, uint32_t bytes) {
    asm volatile("mbarrier.arrive.expect_tx.shared.b64 _, [%0], %1;" :: "r"(a), "r"(bytes) : "memory");
}
__device__ __forceinline__ void mbar_arrive(uint32_t a) {
    asm volatile("mbarrier.arrive.shared.b64 _, [%0];" :: "r"(a) : "memory");
}
__device__ __forceinline__ void mbar_wait(uint32_t a, uint32_t ph) {
    uint32_t done;
    do {
        asm volatile("{\n\t.reg .pred p;\n\t"
                     "mbarrier.try_wait.parity.acquire.cta.shared::cta.b64 p, [%1], %2, 0x989680;\n\t"
                     "selp.b32 %0, 1, 0, p;\n\t}"
                     : "=r"(done) : "r"(a), "r"(ph) : "memory");
    } while (!done);
}
__device__ __forceinline__ void bulk_g2s(uint32_t dst, const void* src,
                                         uint32_t bytes, uint32_t mbar) {
    asm volatile("cp.async.bulk.shared::cluster.global.mbarrier::complete_tx::bytes "
                 "[%0], [%1], %2, [%3];"
                 :: "r"(dst), "l"(src), "r"(bytes), "r"(mbar) : "memory");
}

extern __shared__ float dynsmem[];             // NSTAGES * STAGE_FLOATS

__global__ void __launch_bounds__(BLOCK, 2) asl_kernel(
    const float* __restrict__ cur,
    const float* __restrict__ prev,
    float* __restrict__ out,
    int W, int nstages_total, int nblocks)
{
    __shared__ __align__(8) uint64_t full_bar[NSTAGES];
    __shared__ __align__(8) uint64_t empty_bar[NSTAGES];
    __shared__ float xs[A_DIM];
    __shared__ double wred[BLOCK / 32];
    __shared__ bool is_last;

    const int tid  = threadIdx.x;
    const int warp = tid >> 5;
    const int lane = tid & 31;

    // --- init barriers + current_action segmented log-softmax ---
    if (tid < A_DIM) xs[tid] = cur[tid];
    if (tid == 0) {
        #pragma unroll
        for (int s = 0; s < NSTAGES; s++) {
            mbar_init(s2u(&full_bar[s]), 1);
            mbar_init(s2u(&empty_bar[s]), BLOCK);
        }
    }
    __syncthreads();
    asm volatile("fence.proxy.async.shared::cta;" ::: "memory");
    if (tid < NSEG) {
        const int off[NSEG] = {0, 3, 6, 10, 35, 60};
        const int sz[NSEG]  = {3, 3, 4, 25, 25, 8};
        const int o = off[tid], n = sz[tid];
        float s = 0.f;
        for (int i = 0; i < n; i++) s += __expf(xs[o + i]);
        const float L = __logf(s);
        for (int i = 0; i < n; i++) xs[o + i] -= L;
    }
    __syncthreads();

    int myiters = 0;
    if (blockIdx.x < nstages_total)
        myiters = (nstages_total - 1 - blockIdx.x) / nblocks + 1;

    const char* gbase = reinterpret_cast<const char*>(prev);

    auto issue = [&](int j) {                   // thread 0 only
        const int stage = blockIdx.x + j * nblocks;
        const int slot  = j % NSTAGES;
        const size_t row0 = (size_t)stage * RPS;
        int rows = W - (int)row0; if (rows > RPS) rows = RPS;
        const uint32_t bytes = (uint32_t)rows * (A_DIM * 4);
        const uint32_t fb = s2u(&full_bar[slot]);
        mbar_expect_tx(fb, bytes);
        bulk_g2s(s2u(dynsmem + (size_t)slot * STAGE_FLOATS),
                 gbase + row0 * (A_DIM * 4), bytes, fb);
    };

    if (tid == 0) {
        const int np = myiters < NSTAGES ? myiters : NSTAGES;
        for (int j = 0; j < np; j++) issue(j);
    }

    double acc_d = 0.0;

    for (int j = 0; j < myiters; j++) {
        const int slot = j % NSTAGES;
        const uint32_t ph = (uint32_t)((j / NSTAGES) & 1);
        mbar_wait(s2u(&full_bar[slot]), ph);

        // --- compute: one row per thread, 17 x LDS.128 (conflict-free) ---
        const int stage = blockIdx.x + j * nblocks;
        const int w = stage * RPS + tid;
        if (w < W) {
            const float4* row = reinterpret_cast<const float4*>(
                dynsmem + (size_t)slot * STAGE_FLOATS + tid * A_DIM);
            float s[NSEG] = {0,0,0,0,0,0};
            float a[NSEG] = {0,0,0,0,0,0};
            #pragma unroll
            for (int i = 0; i < 17; i++) {
                const float4 v = row[i];
                const float vv[4] = {v.x, v.y, v.z, v.w};
                #pragma unroll
                for (int k2 = 0; k2 < 4; k2++) {
                    const int idx = 4 * i + k2;
                    const int jj = SEG_OF(idx);          // compile-time
                    const float r = vv[k2];
                    const float e = __expf(r);
                    s[jj] += e;
                    a[jj] = fmaf(e, r - xs[idx], a[jj]);
                }
            }
            const float invn[NSEG] = {1.f/3.f, 1.f/3.f, 1.f/4.f, 1.f/25.f, 1.f/25.f, 1.f/8.f};
            float row_loss = 0.f;
            #pragma unroll
            for (int jj = 0; jj < NSEG; jj++)
                row_loss += invn[jj] * (__fdividef(a[jj], s[jj]) - __logf(s[jj]));
            acc_d += (double)row_loss;
        }

        mbar_arrive(s2u(&empty_bar[slot]));

        if (tid == 0 && j + NSTAGES < myiters) {
            mbar_wait(s2u(&empty_bar[slot]), ph);   // iteration j's arrivals
            issue(j + NSTAGES);
        }
    }

    __syncthreads();

    // --- block reduction (double), deterministic ---
    double d = acc_d;
    #pragma unroll
    for (int st = 16; st > 0; st >>= 1)
        d += __shfl_down_sync(0xFFFFFFFFu, d, st);
    if (lane == 0) wred[warp] = d;
    __syncthreads();
    if (tid == 0) {
        double b = 0.0;
        #pragma unroll
        for (int k = 0; k < BLOCK / 32; k++) b += wred[k];
        g_part[blockIdx.x] = b;
        __threadfence();
        unsigned int t = atomicAdd(&g_count, 1u);
        is_last = (t == (unsigned int)(nblocks - 1));
    }
    __syncthreads();

    if (is_last) {
        double a2 = 0.0;
        for (int k = tid; k < nblocks; k += BLOCK) a2 += g_part[k];
        #pragma unroll
        for (int st = 16; st > 0; st >>= 1)
            a2 += __shfl_down_sync(0xFFFFFFFFu, a2, st);
        if (lane == 0) wred[warp] = a2;
        __syncthreads();
        if (tid == 0) {
            double tot = 0.0;
            #pragma unroll
            for (int k = 0; k < BLOCK / 32; k++) tot += wred[k];
            out[0] = (float)(tot / (double)W);
            g_count = 0;
        }
    }
}

extern "C" void kernel_launch(void* const* d_in, const int* in_sizes, int n_in,
                              void* d_out, int out_size)
{
    const float* cur  = (const float*)d_in[0];   // [68]
    const float* prev = (const float*)d_in[1];   // [W, 68]
    const int W = in_sizes[1] / A_DIM;
    const int nstages_total = (W + RPS - 1) / RPS;

    int nblocks = GRID_MAX;
    if (nblocks > nstages_total) nblocks = nstages_total;

    const int dyn = NSTAGES * STAGE_BYTES;       // 104448 B -> 2 CTAs/SM
    static int configured = 0;
    if (!configured) {
        cudaFuncSetAttribute(asl_kernel,
                             cudaFuncAttributeMaxDynamicSharedMemorySize, dyn);
        configured = 1;
    }

    asl_kernel<<<nblocks, BLOCK, dyn>>>(cur, prev, (float*)d_out,
                                        W, nstages_total, nblocks);
}

// round 13
// speedup vs baseline: 1.0727x; 1.0727x over previous
#include <cuda_runtime.h>
#include <cstdint>

// ActionSmoothingLoss: segmented log-softmax KL
// NVEC = (3,3,4,25,25,8), A = 68, W = 524288
// TMA bulk ring (R9 structure), split dual bulk copies per slot,
// grid=152 (GB300), L2 evict-first streaming hint.

#define A_DIM        68
#define NSEG         6
#define BLOCK        256
#define RPS          256                       // rows per stage
#define HALF_ROWS    128
#define STAGE_FLOATS (RPS * A_DIM)             // 17408
#define STAGE_BYTES  (STAGE_FLOATS * 4)        // 69632
#define HALF_BYTES   (STAGE_BYTES / 2)         // 34816
#define NSTAGES      3
#define GRID_MAX     152                       // GB300 has 152 SMs

__device__ double g_part[GRID_MAX];
__device__ unsigned int g_count = 0;           // returns to 0 each call

#define SEG_OF(k) ((k) < 3 ? 0 : (k) < 6 ? 1 : (k) < 10 ? 2 : (k) < 35 ? 3 : (k) < 60 ? 4 : 5)

__device__ __forceinline__ uint32_t s2u(const void* p) {
    return (uint32_t)__cvta_generic_to_shared(p);
}
__device__ __forceinline__ void mbar_init(uint32_t a, uint32_t cnt) {
    asm volatile("mbarrier.init.shared.b64 [%0], %1;" :: "r"(a), "r"(cnt) : "memory");
}
__device__ __forceinline__ void mbar_expect_tx(uint32_t a, uint32_t bytes) {
    asm volatile("mbarrier.arrive.expect_tx.shared.b64 _, [%0], %1;" :: "r"(a), "r"(bytes) : "memory");
}
__device__ __forceinline__ void mbar_arrive(uint32_t a) {
    asm volatile("mbarrier.arrive.shared.b64 _, [%0];" :: "r"(a) : "memory");
}
__device__ __forceinline__ void mbar_wait(uint32_t a, uint32_t ph) {
    uint32_t done;
    do {
        asm volatile("{\n\t.reg .pred p;\n\t"
                     "mbarrier.try_wait.parity.acquire.cta.shared::cta.b64 p, [%1], %2, 0x989680;\n\t"
                     "selp.b32 %0, 1, 0, p;\n\t}"
                     : "=r"(done) : "r"(a), "r"(ph) : "memory");
    } while (!done);
}
__device__ __forceinline__ uint64_t evict_first_policy() {
    uint64_t pol;
    asm volatile("createpolicy.fractional.L2::evict_first.b64 %0, 1.0;" : "=l"(pol));
    return pol;
}
__device__ __forceinline__ void bulk_g2s_hint(uint32_t dst, const void* src,
                                              uint32_t bytes, uint32_t mbar,
                                              uint64_t pol) {
    asm volatile("cp.async.bulk.shared::cluster.global.mbarrier::complete_tx::bytes.L2::cache_hint "
                 "[%0], [%1], %2, [%3], %4;"
                 :: "r"(dst), "l"(src), "r"(bytes), "r"(mbar), "l"(pol) : "memory");
}

extern __shared__ float dynsmem[];             // NSTAGES * STAGE_FLOATS

__global__ void __launch_bounds__(BLOCK, 1) asl_kernel(
    const float* __restrict__ cur,
    const float* __restrict__ prev,
    float* __restrict__ out,
    int W, int nstages_total, int nblocks)
{
    __shared__ __align__(8) uint64_t full_bar[NSTAGES];
    __shared__ __align__(8) uint64_t empty_bar[NSTAGES];
    __shared__ float xs[A_DIM];
    __shared__ double wred[BLOCK / 32];
    __shared__ bool is_last;

    const int tid  = threadIdx.x;
    const int warp = tid >> 5;
    const int lane = tid & 31;

    // --- init barriers + current_action segmented log-softmax ---
    if (tid < A_DIM) xs[tid] = cur[tid];
    if (tid == 0) {
        #pragma unroll
        for (int s = 0; s < NSTAGES; s++) {
            mbar_init(s2u(&full_bar[s]), 1);
            mbar_init(s2u(&empty_bar[s]), BLOCK);
        }
    }
    __syncthreads();
    asm volatile("fence.proxy.async.shared::cta;" ::: "memory");
    if (tid < NSEG) {
        const int off[NSEG] = {0, 3, 6, 10, 35, 60};
        const int sz[NSEG]  = {3, 3, 4, 25, 25, 8};
        const int o = off[tid], n = sz[tid];
        float s = 0.f;
        for (int i = 0; i < n; i++) s += __expf(xs[o + i]);
        const float L = __logf(s);
        for (int i = 0; i < n; i++) xs[o + i] -= L;
    }
    __syncthreads();

    int myiters = 0;
    if (blockIdx.x < nstages_total)
        myiters = (nstages_total - 1 - blockIdx.x) / nblocks + 1;

    const char* gbase = reinterpret_cast<const char*>(prev);
    const uint64_t pol = evict_first_policy();

    auto issue = [&](int j) {                   // thread 0 only
        const int stage = blockIdx.x + j * nblocks;
        const int slot  = j % NSTAGES;
        const size_t row0 = (size_t)stage * RPS;
        int rows = W - (int)row0; if (rows > RPS) rows = RPS;
        const uint32_t bytes = (uint32_t)rows * (A_DIM * 4);
        const uint32_t fb = s2u(&full_bar[slot]);
        const uint32_t sdst = s2u(dynsmem + (size_t)slot * STAGE_FLOATS);
        const char* gsrc = gbase + row0 * (A_DIM * 4);
        mbar_expect_tx(fb, bytes);
        if (bytes > HALF_BYTES) {               // split into two in-flight bulk ops
            bulk_g2s_hint(sdst, gsrc, HALF_BYTES, fb, pol);
            bulk_g2s_hint(sdst + HALF_BYTES, gsrc + HALF_BYTES,
                          bytes - HALF_BYTES, fb, pol);
        } else {
            bulk_g2s_hint(sdst, gsrc, bytes, fb, pol);
        }
    };

    if (tid == 0) {
        const int np = myiters < NSTAGES ? myiters : NSTAGES;
        for (int j = 0; j < np; j++) issue(j);
    }

    double acc_d = 0.0;

    for (int j = 0; j < myiters; j++) {
        const int slot = j % NSTAGES;
        const uint32_t ph = (uint32_t)((j / NSTAGES) & 1);
        mbar_wait(s2u(&full_bar[slot]), ph);

        // --- compute: one row per thread, 17 x LDS.128 (conflict-free) ---
        const int stage = blockIdx.x + j * nblocks;
        const int w = stage * RPS + tid;
        if (w < W) {
            const float4* row = reinterpret_cast<const float4*>(
                dynsmem + (size_t)slot * STAGE_FLOATS + tid * A_DIM);
            float s[NSEG] = {0,0,0,0,0,0};
            float a[NSEG] = {0,0,0,0,0,0};
            #pragma unroll
            for (int i = 0; i < 17; i++) {
                const float4 v = row[i];
                const float vv[4] = {v.x, v.y, v.z, v.w};
                #pragma unroll
                for (int k2 = 0; k2 < 4; k2++) {
                    const int idx = 4 * i + k2;
                    const int jj = SEG_OF(idx);          // compile-time
                    const float r = vv[k2];
                    const float e = __expf(r);
                    s[jj] += e;
                    a[jj] = fmaf(e, r - xs[idx], a[jj]);
                }
            }
            const float invn[NSEG] = {1.f/3.f, 1.f/3.f, 1.f/4.f, 1.f/25.f, 1.f/25.f, 1.f/8.f};
            float row_loss = 0.f;
            #pragma unroll
            for (int jj = 0; jj < NSEG; jj++)
                row_loss += invn[jj] * (__fdividef(a[jj], s[jj]) - __logf(s[jj]));
            acc_d += (double)row_loss;
        }

        mbar_arrive(s2u(&empty_bar[slot]));

        if (tid == 0 && j + NSTAGES < myiters) {
            mbar_wait(s2u(&empty_bar[slot]), ph);   // iteration j's arrivals
            issue(j + NSTAGES);
        }
    }

    __syncthreads();

    // --- block reduction (double), deterministic ---
    double d = acc_d;
    #pragma unroll
    for (int st = 16; st > 0; st >>= 1)
        d += __shfl_down_sync(0xFFFFFFFFu, d, st);
    if (lane == 0) wred[warp] = d;
    __syncthreads();
    if (tid == 0) {
        double b = 0.0;
        #pragma unroll
        for (int k = 0; k < BLOCK / 32; k++) b += wred[k];
        g_part[blockIdx.x] = b;
        __threadfence();
        unsigned int t = atomicAdd(&g_count, 1u);
        is_last = (t == (unsigned int)(nblocks - 1));
    }
    __syncthreads();

    if (is_last) {
        double a2 = 0.0;
        for (int k = tid; k < nblocks; k += BLOCK) a2 += g_part[k];
        #pragma unroll
        for (int st = 16; st > 0; st >>= 1)
            a2 += __shfl_down_sync(0xFFFFFFFFu, a2, st);
        if (lane == 0) wred[warp] = a2;
        __syncthreads();
        if (tid == 0) {
            double tot = 0.0;
            #pragma unroll
            for (int k = 0; k < BLOCK / 32; k++) tot += wred[k];
            out[0] = (float)(tot / (double)W);
            g_count = 0;
        }
    }
}

extern "C" void kernel_launch(void* const* d_in, const int* in_sizes, int n_in,
                              void* d_out, int out_size)
{
    const float* cur  = (const float*)d_in[0];   // [68]
    const float* prev = (const float*)d_in[1];   // [W, 68]
    const int W = in_sizes[1] / A_DIM;
    const int nstages_total = (W + RPS - 1) / RPS;

    int nblocks = GRID_MAX;
    if (nblocks > nstages_total) nblocks = nstages_total;

    const int dyn = NSTAGES * STAGE_BYTES;       // 208896 B, 1 CTA/SM
    static int configured = 0;
    if (!configured) {
        cudaFuncSetAttribute(asl_kernel,
                             cudaFuncAttributeMaxDynamicSharedMemorySize, dyn);
        configured = 1;
    }

    asl_kernel<<<nblocks, BLOCK, dyn>>>(cur, prev, (float*)d_out,
                                        W, nstages_total, nblocks);
}

// round 14
// speedup vs baseline: 1.0738x; 1.0010x over previous
#include <cuda_runtime.h>
#include <cstdint>

// ActionSmoothingLoss: segmented log-softmax KL
// NVEC = (3,3,4,25,25,8), A = 68, W = 524288
// TMA bulk ring, dedicated producer warp, per-half (128-row) barriers.

#define A_DIM        68
#define NSEG         6
#define NCOMP        256                       // compute threads (rows per stage)
#define BLOCK        288                       // + 1 producer warp
#define RPS          256
#define HROWS        128                       // rows per half
#define STAGE_FLOATS (RPS * A_DIM)             // 17408
#define STAGE_BYTES  (STAGE_FLOATS * 4)        // 69632
#define HALF_BYTES   (HROWS * A_DIM * 4)       // 34816
#define NSTAGES      3
#define GRID_MAX     152

__device__ double g_part[GRID_MAX];
__device__ unsigned int g_count = 0;           // returns to 0 each call

#define SEG_OF(k) ((k) < 3 ? 0 : (k) < 6 ? 1 : (k) < 10 ? 2 : (k) < 35 ? 3 : (k) < 60 ? 4 : 5)

__device__ __forceinline__ uint32_t s2u(const void* p) {
    return (uint32_t)__cvta_generic_to_shared(p);
}
__device__ __forceinline__ void mbar_init(uint32_t a, uint32_t cnt) {
    asm volatile("mbarrier.init.shared.b64 [%0], %1;" :: "r"(a), "r"(cnt) : "memory");
}
__device__ __forceinline__ void mbar_expect_tx(uint32_t a, uint32_t bytes) {
    asm volatile("mbarrier.arrive.expect_tx.shared.b64 _, [%0], %1;" :: "r"(a), "r"(bytes) : "memory");
}
__device__ __forceinline__ void mbar_arrive(uint32_t a) {
    asm volatile("mbarrier.arrive.shared.b64 _, [%0];" :: "r"(a) : "memory");
}
__device__ __forceinline__ void mbar_wait(uint32_t a, uint32_t ph) {
    uint32_t done;
    do {
        asm volatile("{\n\t.reg .pred p;\n\t"
                     "mbarrier.try_wait.parity.acquire.cta.shared::cta.b64 p, [%1], %2, 0x989680;\n\t"
                     "selp.b32 %0, 1, 0, p;\n\t}"
                     : "=r"(done) : "r"(a), "r"(ph) : "memory");
    } while (!done);
}
__device__ __forceinline__ uint64_t evict_first_policy() {
    uint64_t pol;
    asm volatile("createpolicy.fractional.L2::evict_first.b64 %0, 1.0;" : "=l"(pol));
    return pol;
}
__device__ __forceinline__ void bulk_g2s_hint(uint32_t dst, const void* src,
                                              uint32_t bytes, uint32_t mbar,
                                              uint64_t pol) {
    asm volatile("cp.async.bulk.shared::cluster.global.mbarrier::complete_tx::bytes.L2::cache_hint "
                 "[%0], [%1], %2, [%3], %4;"
                 :: "r"(dst), "l"(src), "r"(bytes), "r"(mbar), "l"(pol) : "memory");
}

extern __shared__ float dynsmem[];             // NSTAGES * STAGE_FLOATS

__global__ void __launch_bounds__(BLOCK, 1) asl_kernel(
    const float* __restrict__ cur,
    const float* __restrict__ prev,
    float* __restrict__ out,
    int W, int nstages_total, int nblocks)
{
    __shared__ __align__(8) uint64_t full_bar[NSTAGES][2];
    __shared__ __align__(8) uint64_t empty_bar[NSTAGES][2];
    __shared__ float xs[A_DIM];
    __shared__ double wred[BLOCK / 32];
    __shared__ bool is_last;

    const int tid  = threadIdx.x;
    const int warp = tid >> 5;
    const int lane = tid & 31;

    // --- init barriers + current_action segmented log-softmax ---
    if (tid < A_DIM) xs[tid] = cur[tid];
    if (tid == 0) {
        #pragma unroll
        for (int s = 0; s < NSTAGES; s++) {
            #pragma unroll
            for (int h = 0; h < 2; h++) {
                mbar_init(s2u(&full_bar[s][h]), 1);
                mbar_init(s2u(&empty_bar[s][h]), HROWS);
            }
        }
    }
    __syncthreads();
    asm volatile("fence.proxy.async.shared::cta;" ::: "memory");
    if (tid < NSEG) {
        const int off[NSEG] = {0, 3, 6, 10, 35, 60};
        const int sz[NSEG]  = {3, 3, 4, 25, 25, 8};
        const int o = off[tid], n = sz[tid];
        float s = 0.f;
        for (int i = 0; i < n; i++) s += __expf(xs[o + i]);
        const float L = __logf(s);
        for (int i = 0; i < n; i++) xs[o + i] -= L;
    }
    __syncthreads();

    int myiters = 0;
    if (blockIdx.x < nstages_total)
        myiters = (nstages_total - 1 - blockIdx.x) / nblocks + 1;

    double acc_d = 0.0;

    if (tid >= NCOMP) {
        // ================= producer warp (lane 0 of warp 8) =================
        if (tid == NCOMP) {
            const char* gbase = reinterpret_cast<const char*>(prev);
            const uint64_t pol = evict_first_policy();
            for (int i = 0; i < myiters; i++) {
                const int slot  = i % NSTAGES;
                const int stage = blockIdx.x + i * nblocks;
                const size_t row0 = (size_t)stage * RPS;
                int rows = W - (int)row0; if (rows > RPS) rows = RPS;
                const uint32_t peh = (uint32_t)((i / NSTAGES + 1) & 1);
                #pragma unroll
                for (int h = 0; h < 2; h++) {
                    int hrows = rows - h * HROWS;
                    if (hrows < 0) hrows = 0; if (hrows > HROWS) hrows = HROWS;
                    const uint32_t bytes = (uint32_t)hrows * (A_DIM * 4);
                    const uint32_t fb = s2u(&full_bar[slot][h]);
                    if (i >= NSTAGES) mbar_wait(s2u(&empty_bar[slot][h]), peh);
                    mbar_expect_tx(fb, bytes);
                    if (bytes)
                        bulk_g2s_hint(s2u(dynsmem + (size_t)slot * STAGE_FLOATS
                                          + (size_t)h * (HROWS * A_DIM)),
                                      gbase + (row0 + (size_t)h * HROWS) * (A_DIM * 4),
                                      bytes, fb, pol);
                }
            }
        }
    } else {
        // ================= consumer threads: one row per thread =================
        const int h = tid >> 7;                 // which half this thread's row is in
        for (int j = 0; j < myiters; j++) {
            const int slot = j % NSTAGES;
            const uint32_t ph = (uint32_t)((j / NSTAGES) & 1);
            mbar_wait(s2u(&full_bar[slot][h]), ph);

            const int stage = blockIdx.x + j * nblocks;
            const int w = stage * RPS + tid;
            if (w < W) {
                const float4* row = reinterpret_cast<const float4*>(
                    dynsmem + (size_t)slot * STAGE_FLOATS + tid * A_DIM);
                float s[NSEG] = {0,0,0,0,0,0};
                float a[NSEG] = {0,0,0,0,0,0};
                #pragma unroll
                for (int i = 0; i < 17; i++) {
                    const float4 v = row[i];
                    const float vv[4] = {v.x, v.y, v.z, v.w};
                    #pragma unroll
                    for (int k2 = 0; k2 < 4; k2++) {
                        const int idx = 4 * i + k2;
                        const int jj = SEG_OF(idx);      // compile-time
                        const float r = vv[k2];
                        const float e = __expf(r);
                        s[jj] += e;
                        a[jj] = fmaf(e, r - xs[idx], a[jj]);
                    }
                }
                const float invn[NSEG] = {1.f/3.f, 1.f/3.f, 1.f/4.f, 1.f/25.f, 1.f/25.f, 1.f/8.f};
                float row_loss = 0.f;
                #pragma unroll
                for (int jj = 0; jj < NSEG; jj++)
                    row_loss += invn[jj] * (__fdividef(a[jj], s[jj]) - __logf(s[jj]));
                acc_d += (double)row_loss;
            }

            mbar_arrive(s2u(&empty_bar[slot][h]));
        }
    }

    __syncthreads();

    // --- block reduction (double), deterministic ---
    double d = acc_d;
    #pragma unroll
    for (int st = 16; st > 0; st >>= 1)
        d += __shfl_down_sync(0xFFFFFFFFu, d, st);
    if (lane == 0) wred[warp] = d;
    __syncthreads();
    if (tid == 0) {
        double b = 0.0;
        #pragma unroll
        for (int k = 0; k < BLOCK / 32; k++) b += wred[k];
        g_part[blockIdx.x] = b;
        __threadfence();
        unsigned int t = atomicAdd(&g_count, 1u);
        is_last = (t == (unsigned int)(nblocks - 1));
    }
    __syncthreads();

    if (is_last) {
        double a2 = 0.0;
        for (int k = tid; k < nblocks; k += BLOCK) a2 += g_part[k];
        #pragma unroll
        for (int st = 16; st > 0; st >>= 1)
            a2 += __shfl_down_sync(0xFFFFFFFFu, a2, st);
        if (lane == 0) wred[warp] = a2;
        __syncthreads();
        if (tid == 0) {
            double tot = 0.0;
            #pragma unroll
            for (int k = 0; k < BLOCK / 32; k++) tot += wred[k];
            out[0] = (float)(tot / (double)W);
            g_count = 0;
        }
    }
}

extern "C" void kernel_launch(void* const* d_in, const int* in_sizes, int n_in,
                              void* d_out, int out_size)
{
    const float* cur  = (const float*)d_in[0];   // [68]
    const float* prev = (const float*)d_in[1];   // [W, 68]
    const int W = in_sizes[1] / A_DIM;
    const int nstages_total = (W + RPS - 1) / RPS;

    int nblocks = GRID_MAX;
    if (nblocks > nstages_total) nblocks = nstages_total;

    const int dyn = NSTAGES * STAGE_BYTES;       // 208896 B, 1 CTA/SM
    static int configured = 0;
    if (!configured) {
        cudaFuncSetAttribute(asl_kernel,
                             cudaFuncAttributeMaxDynamicSharedMemorySize, dyn);
        configured = 1;
    }

    asl_kernel<<<nblocks, BLOCK, dyn>>>(cur, prev, (float*)d_out,
                                        W, nstages_total, nblocks);
}